// round 3
// baseline (speedup 1.0000x reference)
#include <cuda_runtime.h>
#include <cstddef>
#include <cstdint>

#define NBATCH 32
#define SEQT   2048
#define DIN    256
#define HID    256
#define GDIM   1024   // 4*HID

// ---------------- scratch (static device allocations, allowed) ----------------
__device__ float g_xg_f[(size_t)NBATCH * SEQT * GDIM];   // 256 MB
__device__ float g_xg_r[(size_t)NBATCH * SEQT * GDIM];   // 256 MB
__device__ float g_h0 [(size_t)NBATCH * SEQT * 2 * HID]; // 128 MB

// ---------------- packed fp32x2 helpers ----------------
__device__ __forceinline__ unsigned long long pack2(float x) {
    unsigned long long r;
    asm("mov.b64 %0, {%1, %1};" : "=l"(r) : "f"(x));
    return r;
}
__device__ __forceinline__ void ffma2(unsigned long long& d,
                                      unsigned long long a, unsigned long long b) {
    asm("fma.rn.f32x2 %0, %1, %2, %0;" : "+l"(d) : "l"(a), "l"(b));
}
__device__ __forceinline__ float tanh_fast(float x) {
    float y;
    asm("tanh.approx.f32 %0, %1;" : "=f"(y) : "f"(x));
    return y;
}
__device__ __forceinline__ float sigm(float x) {
    return 0.5f + 0.5f * tanh_fast(0.5f * x);
}
__device__ __forceinline__ uint32_t f2tf32(float x) {
    uint32_t r;
    asm("cvt.rna.tf32.f32 %0, %1;" : "=r"(r) : "f"(x));
    return r;
}
__device__ __forceinline__ void mma_tf32(float* d, const uint32_t* a, const uint32_t* b) {
    asm("mma.sync.aligned.m16n8k8.row.col.f32.tf32.tf32.f32 "
        "{%0,%1,%2,%3}, {%4,%5,%6,%7}, {%8,%9}, {%0,%1,%2,%3};"
        : "+f"(d[0]), "+f"(d[1]), "+f"(d[2]), "+f"(d[3])
        : "r"(a[0]), "r"(a[1]), "r"(a[2]), "r"(a[3]), "r"(b[0]), "r"(b[1]));
}

// =====================================================================
// tf32 tensor-core GEMM: C[M,N] = A[M,K] @ W[N,K]^T + bias[N]
// 128x128 CTA tile, BK=16, 256 threads = 8 warps (2m x 4n), warp tile 64x32.
// tf32 conversion once at smem staging; inner loop = scalar LDS + HMMA.
// =====================================================================
__global__ __launch_bounds__(256, 2)
void tf32gemm_bias(const float* __restrict__ A, const float* __restrict__ W,
                   const float* __restrict__ bias, float* __restrict__ C, int K)
{
    __shared__ uint32_t As[16][136];   // [k][m], tf32 bits
    __shared__ uint32_t Bs[16][136];   // [k][n], tf32 bits (B[k][n] = W[n][k])

    const int tid  = threadIdx.x;
    const int lane = tid & 31;
    const int warp = tid >> 5;
    const int wm   = warp & 1;          // 0..1  (m dim, 64 rows each)
    const int wn   = warp >> 1;         // 0..3  (n dim, 32 cols each)
    const size_t m0 = (size_t)blockIdx.y * 128;
    const size_t n0 = (size_t)blockIdx.x * 128;
    const int N  = gridDim.x * 128;

    const int lr = tid >> 1;            // tile row 0..127 (for global loads)
    const int lk = (tid & 1) * 8;       // k offset 0 or 8

    const float* Aptr = A + (m0 + lr) * (size_t)K + lk;
    const float* Wptr = W + (n0 + lr) * (size_t)K + lk;

    float4 pa0 = *(const float4*)(Aptr);
    float4 pa1 = *(const float4*)(Aptr + 4);
    float4 pw0 = *(const float4*)(Wptr);
    float4 pw1 = *(const float4*)(Wptr + 4);

    float acc[4][4][4];
    #pragma unroll
    for (int mi = 0; mi < 4; mi++)
        #pragma unroll
        for (int nj = 0; nj < 4; nj++)
            #pragma unroll
            for (int q = 0; q < 4; q++) acc[mi][nj][q] = 0.f;

    const int r = lane >> 2;            // 0..7
    const int c = lane & 3;             // 0..3

    const int nst = K >> 4;
    #pragma unroll 1
    for (int ks = 0; ks < nst; ks++) {
        #pragma unroll
        for (int u = 0; u < 4; u++) {
            As[lk + u][lr]     = f2tf32(((const float*)&pa0)[u]);
            As[lk + 4 + u][lr] = f2tf32(((const float*)&pa1)[u]);
            Bs[lk + u][lr]     = f2tf32(((const float*)&pw0)[u]);
            Bs[lk + 4 + u][lr] = f2tf32(((const float*)&pw1)[u]);
        }
        __syncthreads();

        if (ks + 1 < nst) {
            const float* Ap = Aptr + (size_t)(ks + 1) * 16;
            const float* Wp = Wptr + (size_t)(ks + 1) * 16;
            pa0 = *(const float4*)(Ap);
            pa1 = *(const float4*)(Ap + 4);
            pw0 = *(const float4*)(Wp);
            pw1 = *(const float4*)(Wp + 4);
        }

        #pragma unroll
        for (int slab = 0; slab < 16; slab += 8) {
            uint32_t af[4][4];
            #pragma unroll
            for (int mi = 0; mi < 4; mi++) {
                const int m = wm * 64 + mi * 16 + r;
                af[mi][0] = As[slab + c][m];
                af[mi][1] = As[slab + c][m + 8];
                af[mi][2] = As[slab + c + 4][m];
                af[mi][3] = As[slab + c + 4][m + 8];
            }
            uint32_t bf[4][2];
            #pragma unroll
            for (int nj = 0; nj < 4; nj++) {
                const int n = wn * 32 + nj * 8 + r;
                bf[nj][0] = Bs[slab + c][n];
                bf[nj][1] = Bs[slab + c + 4][n];
            }
            #pragma unroll
            for (int mi = 0; mi < 4; mi++)
                #pragma unroll
                for (int nj = 0; nj < 4; nj++)
                    mma_tf32(acc[mi][nj], af[mi], bf[nj]);
        }
        __syncthreads();
    }

    // epilogue: + bias; c0/c1 = (row, col..col+1), c2/c3 = (row+8, col..col+1)
    #pragma unroll
    for (int mi = 0; mi < 4; mi++) {
        const size_t row = m0 + (size_t)(wm * 64 + mi * 16 + r);
        #pragma unroll
        for (int nj = 0; nj < 4; nj++) {
            const size_t col = n0 + (size_t)(wn * 32 + nj * 8 + c * 2);
            const float2 bz = *(const float2*)&bias[col];
            float2 v0, v1;
            v0.x = acc[mi][nj][0] + bz.x;
            v0.y = acc[mi][nj][1] + bz.y;
            v1.x = acc[mi][nj][2] + bz.x;
            v1.y = acc[mi][nj][3] + bz.y;
            *(float2*)&C[row * (size_t)N + col]       = v0;
            *(float2*)&C[(row + 8) * (size_t)N + col] = v1;
        }
    }
}

// =====================================================================
// Persistent cluster LSTM scan (f32x2 GEMV; h pre-duplicated in smem).
// grid = 128 CTAs = 16 clusters of 8. cluster -> (dir, batch-group of 4).
// =====================================================================
#define CLS 8
#define HSL 32
#define BGR 4
// Wt 128KB + hdup 16KB + part 16KB
#define LSTM_SMEM (256*128*4 + 2*BGR*HID*8 + 8*BGR*128*4)   // 163840 B

__global__ void __cluster_dims__(CLS, 1, 1) __launch_bounds__(256, 1)
lstm_scan(const float* __restrict__ xg_f, const float* __restrict__ xg_r,
          const float* __restrict__ Whh_f, const float* __restrict__ Whh_r,
          float* __restrict__ out)
{
    extern __shared__ float sm[];
    float* Wt = sm;                                            // [256][128] k-major
    unsigned long long* hdup = (unsigned long long*)(sm + 256 * 128); // [2][BGR][256] (h,h)
    float* part = (float*)(hdup + 2 * BGR * HID);              // [8][BGR][128]

    const int tid   = threadIdx.x;
    const int slice = blockIdx.x & 7;        // cluster rank
    const int cid   = blockIdx.x >> 3;
    const int dir   = cid & 1;
    const int bg    = cid >> 1;              // 0..7

    const float* xg  = dir ? xg_r : xg_f;
    const float* Whh = dir ? Whh_r : Whh_f;

    // ---- load W_hh slice transposed: Wt[k][gate*32+j] = Whh[gate*H + slice*32 + j][k]
    {
        const int rr   = tid >> 1;
        const int kh   = (tid & 1) * 128;
        const int gate = rr >> 5;
        const int j    = rr & 31;
        const float* src = Whh + (size_t)(gate * HID + slice * HSL + j) * HID + kh;
        #pragma unroll 8
        for (int k4 = 0; k4 < 128; k4 += 4) {
            const float4 w = *(const float4*)(src + k4);
            Wt[(kh + k4 + 0) * 128 + rr] = w.x;
            Wt[(kh + k4 + 1) * 128 + rr] = w.y;
            Wt[(kh + k4 + 2) * 128 + rr] = w.z;
            Wt[(kh + k4 + 3) * 128 + rr] = w.w;
        }
    }
    for (int i = tid; i < 2 * BGR * HID; i += 256) hdup[i] = 0ull;

    asm volatile("barrier.cluster.arrive.aligned;" ::: "memory");
    asm volatile("barrier.cluster.wait.aligned;" ::: "memory");

    const int kc = tid >> 5;   // k-chunk (warp id)
    const int rg = tid & 31;   // row group (4 rows)
    const int eb = tid >> 5;   // epilogue batch (tid<128)
    const int ej = tid & 31;   // epilogue hidden j

    float c_state = 0.f;
    unsigned hloc[2];
    if (tid < 128) {
        hloc[0] = (unsigned)__cvta_generic_to_shared(
            &hdup[(0 * BGR + eb) * HID + slice * HSL + ej]);
        hloc[1] = (unsigned)__cvta_generic_to_shared(
            &hdup[(1 * BGR + eb) * HID + slice * HSL + ej]);
    }

    int p = 0;
    #pragma unroll 1
    for (int it = 0; it < SEQT; ++it) {
        const int tt = dir ? (SEQT - 1 - it) : it;

        // prefetch xg gate preactivations (latency hidden under GEMV)
        float xgi = 0.f, xgf = 0.f, xgg = 0.f, xgo = 0.f;
        if (tid < 128) {
            const float* xp = xg + ((size_t)(bg * BGR + eb) * SEQT + tt) * GDIM
                                 + slice * HSL + ej;
            xgi = xp[0];
            xgf = xp[HID];
            xgg = xp[2 * HID];
            xgo = xp[3 * HID];
        }

        // ---- GEMV via f32x2: acc2[rp][b] holds rows (4rg+2rp, 4rg+2rp+1)
        unsigned long long acc2[2][4];
        #pragma unroll
        for (int rp = 0; rp < 2; rp++)
            #pragma unroll
            for (int b = 0; b < 4; b++) acc2[rp][b] = 0ull;

        const unsigned long long* hb = hdup + (size_t)(p * BGR) * HID;
        #pragma unroll
        for (int kk = 0; kk < 32; kk += 4) {
            const int k = (kc << 5) + kk;
            // broadcast LDS.128 of pre-duplicated h pairs: hd[u] for 4 batches
            const ulonglong2 h0a = *(const ulonglong2*)(hb + 0 * HID + k);
            const ulonglong2 h0b = *(const ulonglong2*)(hb + 0 * HID + k + 2);
            const ulonglong2 h1a = *(const ulonglong2*)(hb + 1 * HID + k);
            const ulonglong2 h1b = *(const ulonglong2*)(hb + 1 * HID + k + 2);
            const ulonglong2 h2a = *(const ulonglong2*)(hb + 2 * HID + k);
            const ulonglong2 h2b = *(const ulonglong2*)(hb + 2 * HID + k + 2);
            const ulonglong2 h3a = *(const ulonglong2*)(hb + 3 * HID + k);
            const ulonglong2 h3b = *(const ulonglong2*)(hb + 3 * HID + k + 2);
            const unsigned long long hd[4][4] = {
                {h0a.x, h0a.y, h0b.x, h0b.y},
                {h1a.x, h1a.y, h1b.x, h1b.y},
                {h2a.x, h2a.y, h2b.x, h2b.y},
                {h3a.x, h3a.y, h3b.x, h3b.y}};
            #pragma unroll
            for (int u = 0; u < 4; u++) {
                const ulonglong2 wp =
                    *(const ulonglong2*)(Wt + (k + u) * 128 + (rg << 2));
                #pragma unroll
                for (int b = 0; b < 4; b++) {
                    ffma2(acc2[0][b], wp.x, hd[b][u]);
                    ffma2(acc2[1][b], wp.y, hd[b][u]);
                }
            }
        }

        #pragma unroll
        for (int b = 0; b < 4; b++) {
            float* pp = part + (kc * BGR + b) * 128 + (rg << 2);
            *(unsigned long long*)(pp)     = acc2[0][b];
            *(unsigned long long*)(pp + 2) = acc2[1][b];
        }
        __syncthreads();

        // ---- epilogue: reduce 8 k-chunks, activations, state update, broadcast
        float h = 0.f;
        if (tid < 128) {
            float si = xgi, sf = xgf, sg = xgg, so = xgo;
            #pragma unroll
            for (int q = 0; q < 8; q++) {
                const float* pp = part + (q * BGR + eb) * 128 + ej;
                si += pp[0];
                sf += pp[32];
                sg += pp[64];
                so += pp[96];
            }
            const float iv = sigm(si);
            const float fv = sigm(sf);
            const float gv = tanh_fast(sg);
            const float ov = sigm(so);
            c_state = fv * c_state + iv * gv;
            h = ov * tanh_fast(c_state);

            const unsigned long long hp = pack2(h);
            const unsigned la = hloc[p ^ 1];
            #pragma unroll
            for (int rk = 0; rk < CLS; rk++) {
                unsigned ra;
                asm volatile("mapa.shared::cluster.u32 %0, %1, %2;"
                             : "=r"(ra) : "r"(la), "r"(rk));
                asm volatile("st.shared::cluster.b64 [%0], %1;"
                             :: "r"(ra), "l"(hp));
            }
        }

        asm volatile("barrier.cluster.arrive.aligned;" ::: "memory");
        if (tid < 128) {   // hide STG behind the cluster-barrier wait
            out[((size_t)(bg * BGR + eb) * SEQT + tt) * (2 * HID)
                + dir * HID + slice * HSL + ej] = h;
        }
        asm volatile("barrier.cluster.wait.aligned;" ::: "memory");
        p ^= 1;
    }
}

// =====================================================================
extern "C" void kernel_launch(void* const* d_in, const int* in_sizes, int n_in,
                              void* d_out, int out_size)
{
    const float* x      = (const float*)d_in[0];
    const float* Wih_f0 = (const float*)d_in[1];
    const float* Whh_f0 = (const float*)d_in[2];
    const float* b_f0   = (const float*)d_in[3];
    const float* Wih_r0 = (const float*)d_in[4];
    const float* Whh_r0 = (const float*)d_in[5];
    const float* b_r0   = (const float*)d_in[6];
    const float* Wih_f1 = (const float*)d_in[7];
    const float* Whh_f1 = (const float*)d_in[8];
    const float* b_f1   = (const float*)d_in[9];
    const float* Wih_r1 = (const float*)d_in[10];
    const float* Whh_r1 = (const float*)d_in[11];
    const float* b_r1   = (const float*)d_in[12];
    float* out = (float*)d_out;

    float *xg_f, *xg_r, *h0;
    cudaGetSymbolAddress((void**)&xg_f, g_xg_f);
    cudaGetSymbolAddress((void**)&xg_r, g_xg_r);
    cudaGetSymbolAddress((void**)&h0,  g_h0);

    cudaFuncSetAttribute(lstm_scan, cudaFuncAttributeMaxDynamicSharedMemorySize,
                         LSTM_SMEM);

    dim3 blk(256);
    dim3 grid_g(GDIM / 128, (NBATCH * SEQT) / 128);   // (8, 512)

    // layer 0: input projections + scan
    tf32gemm_bias<<<grid_g, blk>>>(x, Wih_f0, b_f0, xg_f, DIN);
    tf32gemm_bias<<<grid_g, blk>>>(x, Wih_r0, b_r0, xg_r, DIN);
    lstm_scan<<<128, blk, LSTM_SMEM>>>(xg_f, xg_r, Whh_f0, Whh_r0, h0);

    // layer 1: input projections over concat(h_f0,h_r0) + scan
    tf32gemm_bias<<<grid_g, blk>>>(h0, Wih_f1, b_f1, xg_f, 2 * HID);
    tf32gemm_bias<<<grid_g, blk>>>(h0, Wih_r1, b_r1, xg_r, 2 * HID);
    lstm_scan<<<128, blk, LSTM_SMEM>>>(xg_f, xg_r, Whh_f1, Whh_r1, out);
}

// round 4
// speedup vs baseline: 1.2413x; 1.2413x over previous
#include <cuda_runtime.h>
#include <cstddef>
#include <cstdint>

#define NBATCH 32
#define SEQT   2048
#define DIN    256
#define HID    256
#define GDIM   1024   // 4*HID

// ---------------- scratch (static device allocations, allowed) ----------------
__device__ float g_xg_f[(size_t)NBATCH * SEQT * GDIM];   // 256 MB
__device__ float g_xg_r[(size_t)NBATCH * SEQT * GDIM];   // 256 MB
__device__ float g_h0 [(size_t)NBATCH * SEQT * 2 * HID]; // 128 MB

// ---------------- helpers ----------------
__device__ __forceinline__ unsigned long long pack2(float x) {
    unsigned long long r;
    asm("mov.b64 %0, {%1, %1};" : "=l"(r) : "f"(x));
    return r;
}
__device__ __forceinline__ void ffma2(unsigned long long& d,
                                      unsigned long long a, unsigned long long b) {
    asm("fma.rn.f32x2 %0, %1, %2, %0;" : "+l"(d) : "l"(a), "l"(b));
}
__device__ __forceinline__ float tanh_fast(float x) {
    float y;
    asm("tanh.approx.f32 %0, %1;" : "=f"(y) : "f"(x));
    return y;
}
__device__ __forceinline__ float sigm(float x) {
    return 0.5f + 0.5f * tanh_fast(0.5f * x);
}
__device__ __forceinline__ uint32_t f2tf32(float x) {
    uint32_t r;
    asm("cvt.rna.tf32.f32 %0, %1;" : "=r"(r) : "f"(x));
    return r;
}
__device__ __forceinline__ void mma_tf32(float* d, const uint32_t* a, const uint32_t* b) {
    asm("mma.sync.aligned.m16n8k8.row.col.f32.tf32.tf32.f32 "
        "{%0,%1,%2,%3}, {%4,%5,%6,%7}, {%8,%9}, {%0,%1,%2,%3};"
        : "+f"(d[0]), "+f"(d[1]), "+f"(d[2]), "+f"(d[3])
        : "r"(a[0]), "r"(a[1]), "r"(a[2]), "r"(a[3]), "r"(b[0]), "r"(b[1]));
}
__device__ __forceinline__ void cp_async16(uint32_t dst, const void* src) {
    asm volatile("cp.async.cg.shared.global [%0], [%1], 16;\n"
                 :: "r"(dst), "l"(src));
}

// =====================================================================
// tf32 tensor-core GEMM v2: C[M,N] = A[M,K] @ W[N,K]^T + bias[N]
// 128x128 CTA tile, BK=32, 3-stage cp.async pipeline, 256 threads
// = 8 warps (2m x 4n), warp tile 64x32.
// smem row-major [row][k] with XOR 16B-chunk swizzle:
//   float index(row, k) = row*32 + (((k>>2) ^ (row&7))<<2) + (k&3)
// -> cp.async 16B-aligned dst AND conflict-free scalar fragment LDS.
// =====================================================================
#define GSTG 3
#define GBUF (128 * 32)   // floats per operand per stage

__global__ __launch_bounds__(256, 2)
void tf32gemm_bias(const float* __restrict__ A, const float* __restrict__ W,
                   const float* __restrict__ bias, float* __restrict__ C, int K)
{
    extern __shared__ float gsm[];
    float* sA = gsm;                 // [GSTG][128*32]
    float* sB = gsm + GSTG * GBUF;   // [GSTG][128*32]

    const int tid  = threadIdx.x;
    const int lane = tid & 31;
    const int warp = tid >> 5;
    const int wm   = warp & 1;          // m dim, 64 rows each
    const int wn   = warp >> 1;         // n dim, 32 cols each
    const size_t m0 = (size_t)blockIdx.y * 128;
    const size_t n0 = (size_t)blockIdx.x * 128;
    const int N  = gridDim.x * 128;

    const int r = lane >> 2;            // 0..7
    const int c = lane & 3;             // 0..3

    // global-load mapping: thread -> (row, 64B half of 128B row)
    const int grow = tid >> 1;          // 0..127
    const int ghalf = tid & 1;          // 0 or 1

    const uint32_t sA_u32 = (uint32_t)__cvta_generic_to_shared(sA);
    const uint32_t sB_u32 = (uint32_t)__cvta_generic_to_shared(sB);

    const float* Ag = A + (m0 + grow) * (size_t)K + ghalf * 16;
    const float* Wg = W + (n0 + grow) * (size_t)K + ghalf * 16;

    const int nst = K >> 5;

    // issue one stage of loads (A+B) into buffer s
    auto load_stage = [&](int ks, int s) {
        const uint32_t baseA = sA_u32 + (uint32_t)(s * GBUF + grow * 32) * 4;
        const uint32_t baseB = sB_u32 + (uint32_t)(s * GBUF + grow * 32) * 4;
        const float* ga = Ag + (size_t)ks * 32;
        const float* gw = Wg + (size_t)ks * 32;
        const int rs = grow & 7;
        #pragma unroll
        for (int j = 0; j < 4; j++) {
            const int q = ghalf * 4 + j;           // 16B chunk 0..7
            const uint32_t off = (uint32_t)((q ^ rs) << 4);
            cp_async16(baseA + off, ga + j * 4);
            cp_async16(baseB + off, gw + j * 4);
        }
    };

    float acc[4][4][4];
    #pragma unroll
    for (int mi = 0; mi < 4; mi++)
        #pragma unroll
        for (int nj = 0; nj < 4; nj++)
            #pragma unroll
            for (int q = 0; q < 4; q++) acc[mi][nj][q] = 0.f;

    // prologue: stages 0 and 1
    load_stage(0, 0);
    asm volatile("cp.async.commit_group;" ::: "memory");
    load_stage(1, 1);
    asm volatile("cp.async.commit_group;" ::: "memory");

    #pragma unroll 1
    for (int ks = 0; ks < nst; ks++) {
        asm volatile("cp.async.wait_group 1;" ::: "memory");
        __syncthreads();

        if (ks + 2 < nst) load_stage(ks + 2, (ks + 2) % GSTG);
        asm volatile("cp.async.commit_group;" ::: "memory");

        const float* bufA = sA + (ks % GSTG) * GBUF;
        const float* bufB = sB + (ks % GSTG) * GBUF;

        #pragma unroll
        for (int slab = 0; slab < 32; slab += 8) {
            const int ch0 = ((slab >> 2) ^ r) << 2;       // chunk for k=slab+c
            const int ch1 = (((slab >> 2) + 1) ^ r) << 2; // chunk for k=slab+c+4
            uint32_t af[4][4];
            #pragma unroll
            for (int mi = 0; mi < 4; mi++) {
                const int m = wm * 64 + mi * 16 + r;
                const int b0 = m * 32 + c;
                const int b8 = (m + 8) * 32 + c;
                af[mi][0] = f2tf32(bufA[b0 + ch0]);
                af[mi][1] = f2tf32(bufA[b8 + ch0]);
                af[mi][2] = f2tf32(bufA[b0 + ch1]);
                af[mi][3] = f2tf32(bufA[b8 + ch1]);
            }
            uint32_t bf[4][2];
            #pragma unroll
            for (int nj = 0; nj < 4; nj++) {
                const int n = wn * 32 + nj * 8 + r;
                const int bb = n * 32 + c;
                bf[nj][0] = f2tf32(bufB[bb + ch0]);
                bf[nj][1] = f2tf32(bufB[bb + ch1]);
            }
            #pragma unroll
            for (int mi = 0; mi < 4; mi++)
                #pragma unroll
                for (int nj = 0; nj < 4; nj++)
                    mma_tf32(acc[mi][nj], af[mi], bf[nj]);
        }
        __syncthreads();
    }

    // epilogue: + bias
    #pragma unroll
    for (int mi = 0; mi < 4; mi++) {
        const size_t row = m0 + (size_t)(wm * 64 + mi * 16 + r);
        #pragma unroll
        for (int nj = 0; nj < 4; nj++) {
            const size_t col = n0 + (size_t)(wn * 32 + nj * 8 + c * 2);
            const float2 bz = *(const float2*)&bias[col];
            float2 v0, v1;
            v0.x = acc[mi][nj][0] + bz.x;
            v0.y = acc[mi][nj][1] + bz.y;
            v1.x = acc[mi][nj][2] + bz.x;
            v1.y = acc[mi][nj][3] + bz.y;
            *(float2*)&C[row * (size_t)N + col]       = v0;
            *(float2*)&C[(row + 8) * (size_t)N + col] = v1;
        }
    }
}
#define GEMM_SMEM (GSTG * GBUF * 2 * 4)   // 98304 B

// =====================================================================
// Persistent cluster LSTM scan — exact Round-2 version (best known).
// grid = 128 CTAs = 16 clusters of 8. cluster -> (dir, batch-group of 4).
// =====================================================================
#define CLS 8
#define HSL 32
#define BGR 4
#define LSTM_SMEM ((256*128 + 2*BGR*HID + 8*BGR*128) * 4)   // 155648 B

__global__ void __cluster_dims__(CLS, 1, 1) __launch_bounds__(256, 1)
lstm_scan(const float* __restrict__ xg_f, const float* __restrict__ xg_r,
          const float* __restrict__ Whh_f, const float* __restrict__ Whh_r,
          float* __restrict__ out)
{
    extern __shared__ float sm[];
    float* Wt   = sm;                        // [256][128] k-major
    float* hbuf = sm + 256 * 128;            // [2][BGR][256]
    float* part = hbuf + 2 * BGR * HID;      // [8][BGR][128]

    const int tid   = threadIdx.x;
    const int slice = blockIdx.x & 7;        // cluster rank
    const int cid   = blockIdx.x >> 3;
    const int dir   = cid & 1;
    const int bg    = cid >> 1;              // 0..7

    const float* xg  = dir ? xg_r : xg_f;
    const float* Whh = dir ? Whh_r : Whh_f;

    // ---- load W_hh slice transposed: Wt[k][gate*32+j] = Whh[gate*H + slice*32 + j][k]
    {
        const int rr   = tid >> 1;
        const int kh   = (tid & 1) * 128;
        const int gate = rr >> 5;
        const int j    = rr & 31;
        const float* src = Whh + (size_t)(gate * HID + slice * HSL + j) * HID + kh;
        #pragma unroll 8
        for (int k4 = 0; k4 < 128; k4 += 4) {
            const float4 w = *(const float4*)(src + k4);
            Wt[(kh + k4 + 0) * 128 + rr] = w.x;
            Wt[(kh + k4 + 1) * 128 + rr] = w.y;
            Wt[(kh + k4 + 2) * 128 + rr] = w.z;
            Wt[(kh + k4 + 3) * 128 + rr] = w.w;
        }
    }
    for (int i = tid; i < 2 * BGR * HID; i += 256) hbuf[i] = 0.f;

    asm volatile("barrier.cluster.arrive.aligned;" ::: "memory");
    asm volatile("barrier.cluster.wait.aligned;" ::: "memory");

    const int kc = tid >> 5;   // k-chunk (warp id)
    const int rg = tid & 31;   // row group (4 rows)
    const int eb = tid >> 5;   // epilogue batch (tid<128)
    const int ej = tid & 31;   // epilogue hidden j

    float c_state = 0.f;
    unsigned hloc[2];
    if (tid < 128) {
        hloc[0] = (unsigned)__cvta_generic_to_shared(
            &hbuf[(0 * BGR + eb) * HID + slice * HSL + ej]);
        hloc[1] = (unsigned)__cvta_generic_to_shared(
            &hbuf[(1 * BGR + eb) * HID + slice * HSL + ej]);
    }

    int p = 0;
    #pragma unroll 1
    for (int it = 0; it < SEQT; ++it) {
        const int tt = dir ? (SEQT - 1 - it) : it;

        // prefetch xg gate preactivations (latency hidden under GEMV)
        float xgi = 0.f, xgf = 0.f, xgg = 0.f, xgo = 0.f;
        if (tid < 128) {
            const float* xp = xg + ((size_t)(bg * BGR + eb) * SEQT + tt) * GDIM
                                 + slice * HSL + ej;
            xgi = xp[0];
            xgf = xp[HID];
            xgg = xp[2 * HID];
            xgo = xp[3 * HID];
        }

        // ---- GEMV via f32x2: acc2[rp][b] holds rows (4rg+2rp, 4rg+2rp+1)
        unsigned long long acc2[2][4];
        #pragma unroll
        for (int rp = 0; rp < 2; rp++)
            #pragma unroll
            for (int b = 0; b < 4; b++) acc2[rp][b] = 0ull;

        const float* hb = hbuf + (p * BGR) * HID;
        #pragma unroll
        for (int kk = 0; kk < 32; kk += 4) {
            const int k = (kc << 5) + kk;
            const float4 h0 = *(const float4*)(hb + 0 * HID + k);
            const float4 h1 = *(const float4*)(hb + 1 * HID + k);
            const float4 h2 = *(const float4*)(hb + 2 * HID + k);
            const float4 h3 = *(const float4*)(hb + 3 * HID + k);
            #pragma unroll
            for (int u = 0; u < 4; u++) {
                const ulonglong2 wp =
                    *(const ulonglong2*)(Wt + (k + u) * 128 + (rg << 2));
                const unsigned long long hd[4] = {
                    pack2(((const float*)&h0)[u]), pack2(((const float*)&h1)[u]),
                    pack2(((const float*)&h2)[u]), pack2(((const float*)&h3)[u])};
                #pragma unroll
                for (int b = 0; b < 4; b++) {
                    ffma2(acc2[0][b], wp.x, hd[b]);
                    ffma2(acc2[1][b], wp.y, hd[b]);
                }
            }
        }

        #pragma unroll
        for (int b = 0; b < 4; b++) {
            float* pp = part + (kc * BGR + b) * 128 + (rg << 2);
            *(unsigned long long*)(pp)     = acc2[0][b];
            *(unsigned long long*)(pp + 2) = acc2[1][b];
        }
        __syncthreads();

        // ---- epilogue: reduce 8 k-chunks, activations, state update, broadcast
        float h = 0.f;
        if (tid < 128) {
            float si = xgi, sf = xgf, sg = xgg, so = xgo;
            #pragma unroll
            for (int q = 0; q < 8; q++) {
                const float* pp = part + (q * BGR + eb) * 128 + ej;
                si += pp[0];
                sf += pp[32];
                sg += pp[64];
                so += pp[96];
            }
            const float iv = sigm(si);
            const float fv = sigm(sf);
            const float gv = tanh_fast(sg);
            const float ov = sigm(so);
            c_state = fv * c_state + iv * gv;
            h = ov * tanh_fast(c_state);

            const unsigned la = hloc[p ^ 1];
            #pragma unroll
            for (int rk = 0; rk < CLS; rk++) {
                unsigned ra;
                asm volatile("mapa.shared::cluster.u32 %0, %1, %2;"
                             : "=r"(ra) : "r"(la), "r"(rk));
                asm volatile("st.shared::cluster.f32 [%0], %1;"
                             :: "r"(ra), "f"(h));
            }
        }

        asm volatile("barrier.cluster.arrive.aligned;" ::: "memory");
        if (tid < 128) {   // hide STG behind the cluster-barrier wait
            out[((size_t)(bg * BGR + eb) * SEQT + tt) * (2 * HID)
                + dir * HID + slice * HSL + ej] = h;
        }
        asm volatile("barrier.cluster.wait.aligned;" ::: "memory");
        p ^= 1;
    }
}

// =====================================================================
extern "C" void kernel_launch(void* const* d_in, const int* in_sizes, int n_in,
                              void* d_out, int out_size)
{
    const float* x      = (const float*)d_in[0];
    const float* Wih_f0 = (const float*)d_in[1];
    const float* Whh_f0 = (const float*)d_in[2];
    const float* b_f0   = (const float*)d_in[3];
    const float* Wih_r0 = (const float*)d_in[4];
    const float* Whh_r0 = (const float*)d_in[5];
    const float* b_r0   = (const float*)d_in[6];
    const float* Wih_f1 = (const float*)d_in[7];
    const float* Whh_f1 = (const float*)d_in[8];
    const float* b_f1   = (const float*)d_in[9];
    const float* Wih_r1 = (const float*)d_in[10];
    const float* Whh_r1 = (const float*)d_in[11];
    const float* b_r1   = (const float*)d_in[12];
    float* out = (float*)d_out;

    float *xg_f, *xg_r, *h0;
    cudaGetSymbolAddress((void**)&xg_f, g_xg_f);
    cudaGetSymbolAddress((void**)&xg_r, g_xg_r);
    cudaGetSymbolAddress((void**)&h0,  g_h0);

    cudaFuncSetAttribute(lstm_scan, cudaFuncAttributeMaxDynamicSharedMemorySize,
                         LSTM_SMEM);
    cudaFuncSetAttribute(tf32gemm_bias, cudaFuncAttributeMaxDynamicSharedMemorySize,
                         GEMM_SMEM);

    dim3 blk(256);
    dim3 grid_g(GDIM / 128, (NBATCH * SEQT) / 128);   // (8, 512)

    // layer 0: input projections + scan
    tf32gemm_bias<<<grid_g, blk, GEMM_SMEM>>>(x, Wih_f0, b_f0, xg_f, DIN);
    tf32gemm_bias<<<grid_g, blk, GEMM_SMEM>>>(x, Wih_r0, b_r0, xg_r, DIN);
    lstm_scan<<<128, blk, LSTM_SMEM>>>(xg_f, xg_r, Whh_f0, Whh_r0, h0);

    // layer 1: input projections over concat(h_f0,h_r0) + scan
    tf32gemm_bias<<<grid_g, blk, GEMM_SMEM>>>(h0, Wih_f1, b_f1, xg_f, 2 * HID);
    tf32gemm_bias<<<grid_g, blk, GEMM_SMEM>>>(h0, Wih_r1, b_r1, xg_r, 2 * HID);
    lstm_scan<<<128, blk, LSTM_SMEM>>>(xg_f, xg_r, Whh_f1, Whh_r1, out);
}

// round 5
// speedup vs baseline: 1.3405x; 1.0799x over previous
#include <cuda_runtime.h>
#include <cstddef>
#include <cstdint>

#define NBATCH 32
#define SEQT   2048
#define DIN    256
#define HID    256
#define GDIM   1024   // 4*HID

// ---------------- scratch (static device allocations, allowed) ----------------
__device__ float g_xg_f[(size_t)NBATCH * SEQT * GDIM];   // 256 MB
__device__ float g_xg_r[(size_t)NBATCH * SEQT * GDIM];   // 256 MB
__device__ float g_h0 [(size_t)NBATCH * SEQT * 2 * HID]; // 128 MB

// ---------------- helpers ----------------
__device__ __forceinline__ unsigned long long pack2(float x) {
    unsigned long long r;
    asm("mov.b64 %0, {%1, %1};" : "=l"(r) : "f"(x));
    return r;
}
__device__ __forceinline__ unsigned long long pack2f(float x, float y) {
    unsigned long long r;
    asm("mov.b64 %0, {%1, %2};" : "=l"(r) : "f"(x), "f"(y));
    return r;
}
__device__ __forceinline__ void ffma2(unsigned long long& d,
                                      unsigned long long a, unsigned long long b) {
    asm("fma.rn.f32x2 %0, %1, %2, %0;" : "+l"(d) : "l"(a), "l"(b));
}
__device__ __forceinline__ float tanh_fast(float x) {
    float y;
    asm("tanh.approx.f32 %0, %1;" : "=f"(y) : "f"(x));
    return y;
}
__device__ __forceinline__ float sigm(float x) {
    return 0.5f + 0.5f * tanh_fast(0.5f * x);
}
__device__ __forceinline__ uint32_t f2tf32(float x) {
    uint32_t r;
    asm("cvt.rna.tf32.f32 %0, %1;" : "=r"(r) : "f"(x));
    return r;
}
__device__ __forceinline__ void mma_tf32(float* d, const uint32_t* a, const uint32_t* b) {
    asm("mma.sync.aligned.m16n8k8.row.col.f32.tf32.tf32.f32 "
        "{%0,%1,%2,%3}, {%4,%5,%6,%7}, {%8,%9}, {%0,%1,%2,%3};"
        : "+f"(d[0]), "+f"(d[1]), "+f"(d[2]), "+f"(d[3])
        : "r"(a[0]), "r"(a[1]), "r"(a[2]), "r"(a[3]), "r"(b[0]), "r"(b[1]));
}
__device__ __forceinline__ void cp_async16(uint32_t dst, const void* src) {
    asm volatile("cp.async.cg.shared.global [%0], [%1], 16;\n"
                 :: "r"(dst), "l"(src));
}

// =====================================================================
// tf32 tensor-core GEMM (unchanged from R4): C = A @ W^T + bias
// =====================================================================
#define GSTG 3
#define GBUF (128 * 32)   // floats per operand per stage

__global__ __launch_bounds__(256, 2)
void tf32gemm_bias(const float* __restrict__ A, const float* __restrict__ W,
                   const float* __restrict__ bias, float* __restrict__ C, int K)
{
    extern __shared__ float gsm[];
    float* sA = gsm;                 // [GSTG][128*32]
    float* sB = gsm + GSTG * GBUF;   // [GSTG][128*32]

    const int tid  = threadIdx.x;
    const int lane = tid & 31;
    const int warp = tid >> 5;
    const int wm   = warp & 1;
    const int wn   = warp >> 1;
    const size_t m0 = (size_t)blockIdx.y * 128;
    const size_t n0 = (size_t)blockIdx.x * 128;
    const int N  = gridDim.x * 128;

    const int r = lane >> 2;
    const int c = lane & 3;

    const int grow = tid >> 1;
    const int ghalf = tid & 1;

    const uint32_t sA_u32 = (uint32_t)__cvta_generic_to_shared(sA);
    const uint32_t sB_u32 = (uint32_t)__cvta_generic_to_shared(sB);

    const float* Ag = A + (m0 + grow) * (size_t)K + ghalf * 16;
    const float* Wg = W + (n0 + grow) * (size_t)K + ghalf * 16;

    const int nst = K >> 5;

    auto load_stage = [&](int ks, int s) {
        const uint32_t baseA = sA_u32 + (uint32_t)(s * GBUF + grow * 32) * 4;
        const uint32_t baseB = sB_u32 + (uint32_t)(s * GBUF + grow * 32) * 4;
        const float* ga = Ag + (size_t)ks * 32;
        const float* gw = Wg + (size_t)ks * 32;
        const int rs = grow & 7;
        #pragma unroll
        for (int j = 0; j < 4; j++) {
            const int q = ghalf * 4 + j;
            const uint32_t off = (uint32_t)((q ^ rs) << 4);
            cp_async16(baseA + off, ga + j * 4);
            cp_async16(baseB + off, gw + j * 4);
        }
    };

    float acc[4][4][4];
    #pragma unroll
    for (int mi = 0; mi < 4; mi++)
        #pragma unroll
        for (int nj = 0; nj < 4; nj++)
            #pragma unroll
            for (int q = 0; q < 4; q++) acc[mi][nj][q] = 0.f;

    load_stage(0, 0);
    asm volatile("cp.async.commit_group;" ::: "memory");
    load_stage(1, 1);
    asm volatile("cp.async.commit_group;" ::: "memory");

    #pragma unroll 1
    for (int ks = 0; ks < nst; ks++) {
        asm volatile("cp.async.wait_group 1;" ::: "memory");
        __syncthreads();

        if (ks + 2 < nst) load_stage(ks + 2, (ks + 2) % GSTG);
        asm volatile("cp.async.commit_group;" ::: "memory");

        const float* bufA = sA + (ks % GSTG) * GBUF;
        const float* bufB = sB + (ks % GSTG) * GBUF;

        #pragma unroll
        for (int slab = 0; slab < 32; slab += 8) {
            const int ch0 = ((slab >> 2) ^ r) << 2;
            const int ch1 = (((slab >> 2) + 1) ^ r) << 2;
            uint32_t af[4][4];
            #pragma unroll
            for (int mi = 0; mi < 4; mi++) {
                const int m = wm * 64 + mi * 16 + r;
                const int b0 = m * 32 + c;
                const int b8 = (m + 8) * 32 + c;
                af[mi][0] = f2tf32(bufA[b0 + ch0]);
                af[mi][1] = f2tf32(bufA[b8 + ch0]);
                af[mi][2] = f2tf32(bufA[b0 + ch1]);
                af[mi][3] = f2tf32(bufA[b8 + ch1]);
            }
            uint32_t bf[4][2];
            #pragma unroll
            for (int nj = 0; nj < 4; nj++) {
                const int n = wn * 32 + nj * 8 + r;
                const int bb = n * 32 + c;
                bf[nj][0] = f2tf32(bufB[bb + ch0]);
                bf[nj][1] = f2tf32(bufB[bb + ch1]);
            }
            #pragma unroll
            for (int mi = 0; mi < 4; mi++)
                #pragma unroll
                for (int nj = 0; nj < 4; nj++)
                    mma_tf32(acc[mi][nj], af[mi], bf[nj]);
        }
        __syncthreads();
    }

    #pragma unroll
    for (int mi = 0; mi < 4; mi++) {
        const size_t row = m0 + (size_t)(wm * 64 + mi * 16 + r);
        #pragma unroll
        for (int nj = 0; nj < 4; nj++) {
            const size_t col = n0 + (size_t)(wn * 32 + nj * 8 + c * 2);
            const float2 bz = *(const float2*)&bias[col];
            float2 v0, v1;
            v0.x = acc[mi][nj][0] + bz.x;
            v0.y = acc[mi][nj][1] + bz.y;
            v1.x = acc[mi][nj][2] + bz.x;
            v1.y = acc[mi][nj][3] + bz.y;
            *(float2*)&C[row * (size_t)N + col]       = v0;
            *(float2*)&C[(row + 8) * (size_t)N + col] = v1;
        }
    }
}
#define GEMM_SMEM (GSTG * GBUF * 2 * 4)   // 98304 B

// =====================================================================
// Persistent cluster LSTM scan v3: W_hh resident in REGISTERS.
// grid = 128 CTAs = 16 clusters of 8. cluster -> (dir, batch-group of 4).
// Thread (warp kc, lane rg) owns rows 4rg..4rg+3 of its CTA's 128-row
// gate slice, k in [kc*32, kc*32+32): 128 weights = 64 packed f32x2 regs.
// Per step: broadcast LDS of h + register FFMA only (no weight LDS).
// =====================================================================
#define CLS 8
#define HSL 32
#define BGR 4
#define LSTM_SMEM ((2*BGR*HID + 8*BGR*128) * 4)   // 24576 B

__global__ void __cluster_dims__(CLS, 1, 1) __launch_bounds__(256, 1)
lstm_scan(const float* __restrict__ xg_f, const float* __restrict__ xg_r,
          const float* __restrict__ Whh_f, const float* __restrict__ Whh_r,
          float* __restrict__ out)
{
    extern __shared__ float sm[];
    float* hbuf = sm;                        // [2][BGR][256]
    float* part = hbuf + 2 * BGR * HID;      // [8][BGR][128]

    const int tid   = threadIdx.x;
    const int slice = blockIdx.x & 7;        // cluster rank
    const int cid   = blockIdx.x >> 3;
    const int dir   = cid & 1;
    const int bg    = cid >> 1;              // 0..7

    const float* xg  = dir ? xg_r : xg_f;
    const float* Whh = dir ? Whh_r : Whh_f;

    const int kc = tid >> 5;   // k-chunk (warp id): k in [kc*32, kc*32+32)
    const int rg = tid & 31;   // row group: rows 4rg..4rg+3 of the slice

    // ---- load this thread's W_hh fragment into registers, pre-packed.
    // slice row r -> global Whh row: (r>>5)*HID + slice*32 + (r&31)
    unsigned long long wr[32][2];   // [local k][row pair]
    {
        const int gate = rg >> 3;
        const int j0   = 4 * (rg & 7);
        const size_t base = (size_t)gate * HID + slice * HSL + j0;
        const float* w0 = Whh + (base + 0) * HID + kc * 32;
        const float* w1 = Whh + (base + 1) * HID + kc * 32;
        const float* w2 = Whh + (base + 2) * HID + kc * 32;
        const float* w3 = Whh + (base + 3) * HID + kc * 32;
        #pragma unroll
        for (int k4 = 0; k4 < 32; k4 += 4) {
            const float4 a = *(const float4*)(w0 + k4);
            const float4 b = *(const float4*)(w1 + k4);
            const float4 c = *(const float4*)(w2 + k4);
            const float4 d = *(const float4*)(w3 + k4);
            #pragma unroll
            for (int u = 0; u < 4; u++) {
                wr[k4 + u][0] = pack2f(((const float*)&a)[u], ((const float*)&b)[u]);
                wr[k4 + u][1] = pack2f(((const float*)&c)[u], ((const float*)&d)[u]);
            }
        }
    }
    for (int i = tid; i < 2 * BGR * HID; i += 256) hbuf[i] = 0.f;

    asm volatile("barrier.cluster.arrive.aligned;" ::: "memory");
    asm volatile("barrier.cluster.wait.aligned;" ::: "memory");

    const int eb = tid >> 5;   // epilogue batch (tid<128)
    const int ej = tid & 31;   // epilogue hidden j

    float c_state = 0.f;
    unsigned hloc[2];
    if (tid < 128) {
        hloc[0] = (unsigned)__cvta_generic_to_shared(
            &hbuf[(0 * BGR + eb) * HID + slice * HSL + ej]);
        hloc[1] = (unsigned)__cvta_generic_to_shared(
            &hbuf[(1 * BGR + eb) * HID + slice * HSL + ej]);
    }

    int p = 0;
    #pragma unroll 1
    for (int it = 0; it < SEQT; ++it) {
        const int tt = dir ? (SEQT - 1 - it) : it;

        // prefetch xg gate preactivations (latency hidden under GEMV)
        float xgi = 0.f, xgf = 0.f, xgg = 0.f, xgo = 0.f;
        if (tid < 128) {
            const float* xp = xg + ((size_t)(bg * BGR + eb) * SEQT + tt) * GDIM
                                 + slice * HSL + ej;
            xgi = xp[0];
            xgf = xp[HID];
            xgg = xp[2 * HID];
            xgo = xp[3 * HID];
        }

        // ---- GEMV from register-resident weights
        unsigned long long acc2[2][4];
        #pragma unroll
        for (int rp = 0; rp < 2; rp++)
            #pragma unroll
            for (int b = 0; b < 4; b++) acc2[rp][b] = 0ull;

        const float* hb = hbuf + (p * BGR) * HID;
        #pragma unroll
        for (int kk = 0; kk < 32; kk += 4) {
            const int k = (kc << 5) + kk;
            const float4 h0 = *(const float4*)(hb + 0 * HID + k);
            const float4 h1 = *(const float4*)(hb + 1 * HID + k);
            const float4 h2 = *(const float4*)(hb + 2 * HID + k);
            const float4 h3 = *(const float4*)(hb + 3 * HID + k);
            #pragma unroll
            for (int u = 0; u < 4; u++) {
                const unsigned long long hd[4] = {
                    pack2(((const float*)&h0)[u]), pack2(((const float*)&h1)[u]),
                    pack2(((const float*)&h2)[u]), pack2(((const float*)&h3)[u])};
                #pragma unroll
                for (int b = 0; b < 4; b++) {
                    ffma2(acc2[0][b], wr[kk + u][0], hd[b]);
                    ffma2(acc2[1][b], wr[kk + u][1], hd[b]);
                }
            }
        }

        #pragma unroll
        for (int b = 0; b < 4; b++) {
            float* pp = part + (kc * BGR + b) * 128 + (rg << 2);
            *(unsigned long long*)(pp)     = acc2[0][b];
            *(unsigned long long*)(pp + 2) = acc2[1][b];
        }
        __syncthreads();

        // ---- epilogue: reduce 8 k-chunks, activations, state update, broadcast
        float h = 0.f;
        if (tid < 128) {
            float si = xgi, sf = xgf, sg = xgg, so = xgo;
            #pragma unroll
            for (int q = 0; q < 8; q++) {
                const float* pp = part + (q * BGR + eb) * 128 + ej;
                si += pp[0];
                sf += pp[32];
                sg += pp[64];
                so += pp[96];
            }
            const float iv = sigm(si);
            const float fv = sigm(sf);
            const float gv = tanh_fast(sg);
            const float ov = sigm(so);
            c_state = fv * c_state + iv * gv;
            h = ov * tanh_fast(c_state);

            const unsigned la = hloc[p ^ 1];
            #pragma unroll
            for (int rk = 0; rk < CLS; rk++) {
                unsigned ra;
                asm volatile("mapa.shared::cluster.u32 %0, %1, %2;"
                             : "=r"(ra) : "r"(la), "r"(rk));
                asm volatile("st.shared::cluster.f32 [%0], %1;"
                             :: "r"(ra), "f"(h));
            }
        }

        asm volatile("barrier.cluster.arrive.aligned;" ::: "memory");
        if (tid < 128) {   // hide STG behind the cluster-barrier wait
            out[((size_t)(bg * BGR + eb) * SEQT + tt) * (2 * HID)
                + dir * HID + slice * HSL + ej] = h;
        }
        asm volatile("barrier.cluster.wait.aligned;" ::: "memory");
        p ^= 1;
    }
}

// =====================================================================
extern "C" void kernel_launch(void* const* d_in, const int* in_sizes, int n_in,
                              void* d_out, int out_size)
{
    const float* x      = (const float*)d_in[0];
    const float* Wih_f0 = (const float*)d_in[1];
    const float* Whh_f0 = (const float*)d_in[2];
    const float* b_f0   = (const float*)d_in[3];
    const float* Wih_r0 = (const float*)d_in[4];
    const float* Whh_r0 = (const float*)d_in[5];
    const float* b_r0   = (const float*)d_in[6];
    const float* Wih_f1 = (const float*)d_in[7];
    const float* Whh_f1 = (const float*)d_in[8];
    const float* b_f1   = (const float*)d_in[9];
    const float* Wih_r1 = (const float*)d_in[10];
    const float* Whh_r1 = (const float*)d_in[11];
    const float* b_r1   = (const float*)d_in[12];
    float* out = (float*)d_out;

    float *xg_f, *xg_r, *h0;
    cudaGetSymbolAddress((void**)&xg_f, g_xg_f);
    cudaGetSymbolAddress((void**)&xg_r, g_xg_r);
    cudaGetSymbolAddress((void**)&h0,  g_h0);

    cudaFuncSetAttribute(lstm_scan, cudaFuncAttributeMaxDynamicSharedMemorySize,
                         LSTM_SMEM);
    cudaFuncSetAttribute(tf32gemm_bias, cudaFuncAttributeMaxDynamicSharedMemorySize,
                         GEMM_SMEM);

    dim3 blk(256);
    dim3 grid_g(GDIM / 128, (NBATCH * SEQT) / 128);   // (8, 512)

    // layer 0: input projections + scan
    tf32gemm_bias<<<grid_g, blk, GEMM_SMEM>>>(x, Wih_f0, b_f0, xg_f, DIN);
    tf32gemm_bias<<<grid_g, blk, GEMM_SMEM>>>(x, Wih_r0, b_r0, xg_r, DIN);
    lstm_scan<<<128, blk, LSTM_SMEM>>>(xg_f, xg_r, Whh_f0, Whh_r0, h0);

    // layer 1: input projections over concat(h_f0,h_r0) + scan
    tf32gemm_bias<<<grid_g, blk, GEMM_SMEM>>>(h0, Wih_f1, b_f1, xg_f, 2 * HID);
    tf32gemm_bias<<<grid_g, blk, GEMM_SMEM>>>(h0, Wih_r1, b_r1, xg_r, 2 * HID);
    lstm_scan<<<128, blk, LSTM_SMEM>>>(xg_f, xg_r, Whh_f1, Whh_r1, out);
}